// round 2
// baseline (speedup 1.0000x reference)
#include <cuda_runtime.h>
#include <cuda_bf16.h>
#include <cstdint>

#define BATCH 16384
#define TDIM 1024
#define IDIM 2048

// tcgen05 is an arch-specific (sm_103a/sm_100a) feature. The harness also runs a
// generic sm_103 compilation pass, so guard all tcgen05 code with the
// arch-specific feature macros and provide a SIMT fallback for the generic pass.
#if defined(__CUDA_ARCH_FEAT_SM103_ALL) || defined(__CUDA_ARCH_FEAT_SM100_ALL) || defined(__CUDA_ARCH_SPECIFIC__)
#define HAS_TCGEN05 1
#else
#define HAS_TCGEN05 0
#endif

// ======================= device scratch (static, no allocs) =======================
__device__ __nv_bfloat16 g_text_hi[BATCH * TDIM];
__device__ __nv_bfloat16 g_text_lo[BATCH * TDIM];
__device__ __nv_bfloat16 g_img_hi[BATCH * IDIM];
__device__ __nv_bfloat16 g_img_lo[BATCH * IDIM];
__device__ __nv_bfloat16 g_wq_hi[TDIM * TDIM];
__device__ __nv_bfloat16 g_wq_lo[TDIM * TDIM];
__device__ __nv_bfloat16 g_wk_hi[TDIM * IDIM];
__device__ __nv_bfloat16 g_wk_lo[TDIM * IDIM];
__device__ __nv_bfloat16 g_wv_hi[TDIM * IDIM];
__device__ __nv_bfloat16 g_wv_lo[TDIM * IDIM];
__device__ float g_Q[BATCH * TDIM];
__device__ float g_K[BATCH * TDIM];
__device__ float g_V[BATCH * TDIM];

// ======================= PTX helpers (used only in HAS_TCGEN05 regions) ==========
__device__ __forceinline__ uint32_t smem_u32(const void* p) {
    uint32_t a;
    asm("{ .reg .u64 t; cvta.to.shared.u64 t, %1; cvt.u32.u64 %0, t; }" : "=r"(a) : "l"(p));
    return a;
}

__device__ __forceinline__ uint32_t elect_one_pred() {
    uint32_t pred;
    asm volatile(
        "{\n\t.reg .pred p;\n\telect.sync _|p, 0xFFFFFFFF;\n\tselp.b32 %0, 1, 0, p;\n\t}"
        : "=r"(pred));
    return pred;
}

#define TCGEN05_ALLOC(smem_result_addr, nCols) \
    asm volatile("tcgen05.alloc.cta_group::1.sync.aligned.shared::cta.b32 [%0], %1;" \
                 :: "r"((uint32_t)(smem_result_addr)), "r"((uint32_t)(nCols)) : "memory")
#define TCGEN05_DEALLOC(tmem_addr, nCols) \
    asm volatile("tcgen05.dealloc.cta_group::1.sync.aligned.b32 %0, %1;" \
                 :: "r"(tmem_addr), "r"((uint32_t)(nCols)))
#define TCGEN05_RELINQUISH() \
    asm volatile("tcgen05.relinquish_alloc_permit.cta_group::1.sync.aligned;")
#define TCGEN05_COMMIT(mbar) \
    asm volatile("tcgen05.commit.cta_group::1.mbarrier::arrive::one.shared::cluster.b64 [%0];" \
                 :: "r"((uint32_t)(mbar)) : "memory")
#define TCGEN05_FENCE_BEFORE() asm volatile("tcgen05.fence::before_thread_sync;" ::: "memory")
#define TCGEN05_FENCE_AFTER()  asm volatile("tcgen05.fence::after_thread_sync;" ::: "memory")
#define TCGEN05_WAIT_LD()      asm volatile("tcgen05.wait::ld.sync.aligned;" ::: "memory")

#define MBARRIER_INIT(mbar, count) \
    asm volatile("mbarrier.init.shared.b64 [%0], %1;" \
                 :: "r"((uint32_t)(mbar)), "r"((uint32_t)(count)) : "memory")
#define MBARRIER_INVAL(mbar) \
    asm volatile("mbarrier.inval.shared.b64 [%0];" :: "r"((uint32_t)(mbar)) : "memory")

#define MBARRIER_WAIT_PARITY(mbar_smem_addr, phase_parity) do { \
    uint32_t _mbar = (uint32_t)(mbar_smem_addr); \
    uint32_t _parity = (uint32_t)(phase_parity); \
    uint32_t _done; \
    asm volatile( \
        "{\n\t.reg .pred p;\n\t" \
        "mbarrier.try_wait.parity.acquire.cta.shared::cta.b64 p, [%1], %2;\n\t" \
        "selp.b32 %0, 1, 0, p;\n\t}" \
        : "=r"(_done) : "r"(_mbar), "r"(_parity) : "memory"); \
    if (!_done) { \
        asm volatile( \
            "{\n\t.reg .pred P1;\n\t" \
            "WAIT_LOOP_%=:\n\t" \
            "mbarrier.try_wait.parity.acquire.cta.shared::cta.b64 P1, [%0], %1, 0x989680;\n\t" \
            "@P1 bra.uni WAIT_DONE_%=;\n\t" \
            "bra.uni WAIT_LOOP_%=;\n\t" \
            "WAIT_DONE_%=:\n\t}" \
            :: "r"(_mbar), "r"(_parity) : "memory"); \
    } \
} while (0)

#define TCGEN05_LD_32X32B_X32(r, tmem_addr) \
    asm volatile( \
        "tcgen05.ld.sync.aligned.32x32b.x32.b32 " \
        "{%0, %1, %2, %3, %4, %5, %6, %7, " \
        " %8, %9, %10, %11, %12, %13, %14, %15, " \
        " %16, %17, %18, %19, %20, %21, %22, %23, " \
        " %24, %25, %26, %27, %28, %29, %30, %31}, [%32];" \
        : "=r"((r)[0]),  "=r"((r)[1]),  "=r"((r)[2]),  "=r"((r)[3]), \
          "=r"((r)[4]),  "=r"((r)[5]),  "=r"((r)[6]),  "=r"((r)[7]), \
          "=r"((r)[8]),  "=r"((r)[9]),  "=r"((r)[10]), "=r"((r)[11]), \
          "=r"((r)[12]), "=r"((r)[13]), "=r"((r)[14]), "=r"((r)[15]), \
          "=r"((r)[16]), "=r"((r)[17]), "=r"((r)[18]), "=r"((r)[19]), \
          "=r"((r)[20]), "=r"((r)[21]), "=r"((r)[22]), "=r"((r)[23]), \
          "=r"((r)[24]), "=r"((r)[25]), "=r"((r)[26]), "=r"((r)[27]), \
          "=r"((r)[28]), "=r"((r)[29]), "=r"((r)[30]), "=r"((r)[31]) \
        : "r"(tmem_addr))

#define SMEM_SWIZZLE_128B(byte_offset) ((byte_offset) ^ (((byte_offset) >> 3) & 0x70))

static constexpr uint64_t SMEM_DESC_BASE_SW128 =
    (uint64_t(2) << 61) | (uint64_t(1) << 46) | (uint64_t(64) << 32) | (uint64_t(1) << 16);
#define MAKE_SMEM_DESC(base_addr) \
    (SMEM_DESC_BASE_SW128 | ((uint64_t)((base_addr) >> 4) & 0x3FFF))

#if HAS_TCGEN05
// cg1 SS-mode bf16 MMA (A desc, B desc), fp32 accum
__device__ __forceinline__ void mma_f16_ss(uint32_t d_tmem, uint64_t a_desc, uint64_t b_desc,
                                           uint32_t idesc, uint32_t en) {
    asm volatile(
        "{\n\t.reg .pred p;\n\tsetp.ne.u32 p, %5, 0;\n\t"
        "tcgen05.mma.cta_group::1.kind::f16 [%0], %1, %2, %3, {%4, %4, %4, %4}, p;\n\t}"
        :: "r"(d_tmem), "l"(a_desc), "l"(b_desc), "r"(idesc), "r"(0u), "r"(en)
        : "memory");
}
#endif

// ======================= split fp32 -> bf16 hi/lo =======================
__global__ void split_kernel(const float* __restrict__ src,
                             __nv_bfloat16* __restrict__ hi,
                             __nv_bfloat16* __restrict__ lo, int n4) {
    int i = blockIdx.x * blockDim.x + threadIdx.x;
    if (i >= n4) return;
    float4 x = ((const float4*)src)[i];
    __nv_bfloat16 h0 = __float2bfloat16_rn(x.x);
    __nv_bfloat16 h1 = __float2bfloat16_rn(x.y);
    __nv_bfloat16 h2 = __float2bfloat16_rn(x.z);
    __nv_bfloat16 h3 = __float2bfloat16_rn(x.w);
    __nv_bfloat16 l0 = __float2bfloat16_rn(x.x - __bfloat162float(h0));
    __nv_bfloat16 l1 = __float2bfloat16_rn(x.y - __bfloat162float(h1));
    __nv_bfloat16 l2 = __float2bfloat16_rn(x.z - __bfloat162float(h2));
    __nv_bfloat16 l3 = __float2bfloat16_rn(x.w - __bfloat162float(h3));
    __nv_bfloat162* hp = (__nv_bfloat162*)hi;
    __nv_bfloat162* lp = (__nv_bfloat162*)lo;
    hp[2 * i]     = __halves2bfloat162(h0, h1);
    hp[2 * i + 1] = __halves2bfloat162(h2, h3);
    lp[2 * i]     = __halves2bfloat162(l0, l1);
    lp[2 * i + 1] = __halves2bfloat162(l2, l3);
}

// ======================= GEMM: C[M,N] = A[M,K] @ B[N,K]^T + bias =======================
// tcgen05 path: 3x bf16 split (A_hi*B_hi + A_hi*B_lo + A_lo*B_hi), fp32 TMEM accum.
// CTA tile: 256(M) x 128(N), K-chunk = 64 elems (128B rows, SW128).
#define OFF_MBAR 8
#define OFF_AHI 1024
#define OFF_ALO (1024 + 32768)
#define OFF_BHI (1024 + 65536)
#define OFF_BLO (1024 + 81920)
#define GEMM_SMEM (1024 + 98304)

// idesc: dtype F32, a/b BF16, N=128 -> (N/8)<<17, M=128 -> (M/16)<<24
#define GEMM_IDESC 0x8200490u

__global__ __launch_bounds__(256) void gemm3_kernel(
    const __nv_bfloat16* __restrict__ Ahi, const __nv_bfloat16* __restrict__ Alo,
    const __nv_bfloat16* __restrict__ Bhi, const __nv_bfloat16* __restrict__ Blo,
    const float* __restrict__ bias, float* __restrict__ C, int Kg, int Ng) {
#if HAS_TCGEN05
    extern __shared__ char smem[];
    uint32_t sb = smem_u32(smem);
    const int tid = threadIdx.x;
    const int wid = tid >> 5;
    const int lane = tid & 31;
    const int m0 = blockIdx.y * 256;
    const int n0 = blockIdx.x * 128;

    if (wid == 0) TCGEN05_ALLOC(sb, 256);
    __syncthreads();
    uint32_t tmem_base;
    asm volatile("ld.shared.b32 %0, [%1];" : "=r"(tmem_base) : "r"(sb));
    if (wid == 0) TCGEN05_RELINQUISH();
    if (tid == 0) MBARRIER_INIT(sb + OFF_MBAR, 1);
    __syncthreads();

    const int nk = Kg >> 6;
    for (int kc = 0; kc < nk; ++kc) {
        if (kc) MBARRIER_WAIT_PARITY(sb + OFF_MBAR, (kc - 1) & 1);
        const int k0 = kc << 6;
        // A tiles: 256 rows x 64 bf16 (hi+lo)
        #pragma unroll
        for (int i = 0; i < 8; ++i) {
            int idx = tid + i * 256;
            int row = idx >> 3, q = idx & 7;
            size_t gi = (((size_t)(m0 + row) * Kg + k0) >> 3) + q;
            uint32_t sw = SMEM_SWIZZLE_128B(row * 128 + q * 16);
            *(uint4*)(smem + OFF_AHI + sw) = ((const uint4*)Ahi)[gi];
            *(uint4*)(smem + OFF_ALO + sw) = ((const uint4*)Alo)[gi];
        }
        // B tiles: 128 rows x 64 bf16 (hi+lo)
        #pragma unroll
        for (int i = 0; i < 4; ++i) {
            int idx = tid + i * 256;
            int row = idx >> 3, q = idx & 7;
            size_t gi = (((size_t)(n0 + row) * Kg + k0) >> 3) + q;
            uint32_t sw = SMEM_SWIZZLE_128B(row * 128 + q * 16);
            *(uint4*)(smem + OFF_BHI + sw) = ((const uint4*)Bhi)[gi];
            *(uint4*)(smem + OFF_BLO + sw) = ((const uint4*)Blo)[gi];
        }
        asm volatile("fence.proxy.async.shared::cta;" ::: "memory");
        __syncthreads();

        if (wid == 0 && elect_one_pred()) {
            uint64_t dAhi = MAKE_SMEM_DESC(sb + OFF_AHI);
            uint64_t dAlo = MAKE_SMEM_DESC(sb + OFF_ALO);
            uint64_t dBhi = MAKE_SMEM_DESC(sb + OFF_BHI);
            uint64_t dBlo = MAKE_SMEM_DESC(sb + OFF_BLO);
            #pragma unroll
            for (int sub = 0; sub < 2; ++sub) {
                uint32_t d = tmem_base + sub * 128;
                uint64_t ao = (uint64_t)sub * 1024;  // +16KB in 16B units
                #pragma unroll
                for (int ks = 0; ks < 4; ++ks)
                    mma_f16_ss(d, dAhi + ao + ks * 2, dBhi + ks * 2, GEMM_IDESC,
                               (kc == 0 && ks == 0) ? 0u : 1u);
                #pragma unroll
                for (int ks = 0; ks < 4; ++ks)
                    mma_f16_ss(d, dAhi + ao + ks * 2, dBlo + ks * 2, GEMM_IDESC, 1u);
                #pragma unroll
                for (int ks = 0; ks < 4; ++ks)
                    mma_f16_ss(d, dAlo + ao + ks * 2, dBhi + ks * 2, GEMM_IDESC, 1u);
            }
            TCGEN05_COMMIT(sb + OFF_MBAR);
        }
    }

    MBARRIER_WAIT_PARITY(sb + OFF_MBAR, (nk - 1) & 1);
    TCGEN05_FENCE_AFTER();

    // Epilogue: warps 0-3 -> D0 (rows m0..m0+127), warps 4-7 -> D1 (rows m0+128..)
    {
        int sub = wid >> 2, w4 = wid & 3;
        int row = m0 + sub * 128 + w4 * 32 + lane;
        float* Crow = C + (size_t)row * Ng + n0;
        uint32_t cb = tmem_base + sub * 128;
        #pragma unroll
        for (int g2 = 0; g2 < 4; ++g2) {
            uint32_t r[32];
            TCGEN05_LD_32X32B_X32(r, cb + g2 * 32);
            TCGEN05_WAIT_LD();
            #pragma unroll
            for (int c = 0; c < 32; ++c)
                Crow[g2 * 32 + c] = __uint_as_float(r[c]) + __ldg(&bias[n0 + g2 * 32 + c]);
        }
    }
    TCGEN05_FENCE_BEFORE();
    __syncthreads();
    if (tid == 0) MBARRIER_INVAL(sb + OFF_MBAR);
    if (wid == 0) TCGEN05_DEALLOC(tmem_base, 256);
#else
    // ---------- SIMT fallback (generic sm_103 pass; correct, no tcgen05) ----------
    extern __shared__ char smem[];
    float* sA = (float*)smem;                         // [128][33]
    float* sB = (float*)(smem + 128 * 33 * 4);        // [128][33]
    const int tid = threadIdx.x;
    const int tx = tid & 15, ty = tid >> 4;
    const int m0 = blockIdx.y * 256;
    const int n0 = blockIdx.x * 128;

    for (int h = 0; h < 2; ++h) {
        float acc[8][8];
        #pragma unroll
        for (int i = 0; i < 8; ++i)
            #pragma unroll
            for (int j = 0; j < 8; ++j) acc[i][j] = 0.f;

        for (int k0 = 0; k0 < Kg; k0 += 32) {
            __syncthreads();
            for (int i = tid; i < 128 * 32; i += 256) {
                int r = i >> 5, c = i & 31;
                size_t ga = (size_t)(m0 + h * 128 + r) * Kg + k0 + c;
                size_t gb = (size_t)(n0 + r) * Kg + k0 + c;
                sA[r * 33 + c] = __bfloat162float(Ahi[ga]) + __bfloat162float(Alo[ga]);
                sB[r * 33 + c] = __bfloat162float(Bhi[gb]) + __bfloat162float(Blo[gb]);
            }
            __syncthreads();
            #pragma unroll 8
            for (int kk = 0; kk < 32; ++kk) {
                float a[8], bb[8];
                #pragma unroll
                for (int i = 0; i < 8; ++i) a[i] = sA[(ty * 8 + i) * 33 + kk];
                #pragma unroll
                for (int j = 0; j < 8; ++j) bb[j] = sB[(tx * 8 + j) * 33 + kk];
                #pragma unroll
                for (int i = 0; i < 8; ++i)
                    #pragma unroll
                    for (int j = 0; j < 8; ++j) acc[i][j] = fmaf(a[i], bb[j], acc[i][j]);
            }
        }
        #pragma unroll
        for (int i = 0; i < 8; ++i) {
            int row = m0 + h * 128 + ty * 8 + i;
            float* Crow = C + (size_t)row * Ng + n0 + tx * 8;
            #pragma unroll
            for (int j = 0; j < 8; ++j)
                Crow[j] = acc[i][j] + bias[n0 + tx * 8 + j];
        }
    }
#endif
}

// ======================= fused attention + residual + LayerNorm =======================
// One block per batch row. 8 heads x 128 dims; scores are 8x8.
__global__ __launch_bounds__(256) void attn_ln_kernel(
    const float* __restrict__ Q, const float* __restrict__ K, const float* __restrict__ V,
    const float* __restrict__ text, const float* __restrict__ gamma,
    const float* __restrict__ beta, float* __restrict__ out) {
    __shared__ float sQ[1024], sK[1024], sV[1024];
    __shared__ float sAttn[8][8];
    __shared__ float red[16];
    const int b = blockIdx.x;
    const int tid = threadIdx.x;
    const int w = tid >> 5, lane = tid & 31;
    const size_t base = (size_t)b * 1024;

    for (int i = tid; i < 1024; i += 256) {
        sQ[i] = Q[base + i];
        sK[i] = K[base + i];
        sV[i] = V[base + i];
    }
    __syncthreads();

    // warp w computes scores for head h=w over all g
    float sc[8];
    #pragma unroll
    for (int g = 0; g < 8; ++g) {
        float s = 0.f;
        #pragma unroll
        for (int d = 0; d < 4; ++d) {
            int dd = lane + d * 32;
            s += sQ[w * 128 + dd] * sK[g * 128 + dd];
        }
        #pragma unroll
        for (int o = 16; o; o >>= 1) s += __shfl_xor_sync(0xffffffffu, s, o);
        sc[g] = s * 0.08838834764831845f;  // 1/sqrt(128)
    }
    float m = sc[0];
    #pragma unroll
    for (int g = 1; g < 8; ++g) m = fmaxf(m, sc[g]);
    float den = 0.f;
    #pragma unroll
    for (int g = 0; g < 8; ++g) { sc[g] = __expf(sc[g] - m); den += sc[g]; }
    float inv = 1.f / den;
    if (lane < 8) sAttn[w][lane] = sc[lane] * inv;
    __syncthreads();

    // attended + residual; accumulate moments
    float xv[4];
    float sum = 0.f, sumsq = 0.f;
    #pragma unroll
    for (int j = 0; j < 4; ++j) {
        int d = tid + j * 256;
        int h = d >> 7, dd = d & 127;
        float a = 0.f;
        #pragma unroll
        for (int g = 0; g < 8; ++g) a += sAttn[h][g] * sV[g * 128 + dd];
        float x = text[base + d] + a;
        xv[j] = x;
        sum += x;
        sumsq += x * x;
    }
    #pragma unroll
    for (int o = 16; o; o >>= 1) {
        sum += __shfl_xor_sync(0xffffffffu, sum, o);
        sumsq += __shfl_xor_sync(0xffffffffu, sumsq, o);
    }
    if (lane == 0) { red[w] = sum; red[8 + w] = sumsq; }
    __syncthreads();
    float ts = 0.f, tq = 0.f;
    #pragma unroll
    for (int i = 0; i < 8; ++i) { ts += red[i]; tq += red[8 + i]; }
    float mu = ts * (1.f / 1024.f);
    float var = tq * (1.f / 1024.f) - mu * mu;
    float rstd = rsqrtf(var + 1e-5f);
    #pragma unroll
    for (int j = 0; j < 4; ++j) {
        int d = tid + j * 256;
        out[base + d] = (xv[j] - mu) * rstd * gamma[d] + beta[d];
    }
}

// ======================= host =======================
extern "C" void kernel_launch(void* const* d_in, const int* in_sizes, int n_in,
                              void* d_out, int out_size) {
    const float* text  = (const float*)d_in[0];
    const float* image = (const float*)d_in[1];
    const float* Wq    = (const float*)d_in[2];
    const float* bq    = (const float*)d_in[3];
    const float* Wk    = (const float*)d_in[4];
    const float* bk    = (const float*)d_in[5];
    const float* Wv    = (const float*)d_in[6];
    const float* bv    = (const float*)d_in[7];
    const float* gamma = (const float*)d_in[8];
    const float* beta  = (const float*)d_in[9];
    float* out = (float*)d_out;

    void *t_hi, *t_lo, *i_hi, *i_lo;
    void *wq_hi, *wq_lo, *wk_hi, *wk_lo, *wv_hi, *wv_lo;
    void *pQ, *pK, *pV;
    cudaGetSymbolAddress(&t_hi, g_text_hi);
    cudaGetSymbolAddress(&t_lo, g_text_lo);
    cudaGetSymbolAddress(&i_hi, g_img_hi);
    cudaGetSymbolAddress(&i_lo, g_img_lo);
    cudaGetSymbolAddress(&wq_hi, g_wq_hi);
    cudaGetSymbolAddress(&wq_lo, g_wq_lo);
    cudaGetSymbolAddress(&wk_hi, g_wk_hi);
    cudaGetSymbolAddress(&wk_lo, g_wk_lo);
    cudaGetSymbolAddress(&wv_hi, g_wv_hi);
    cudaGetSymbolAddress(&wv_lo, g_wv_lo);
    cudaGetSymbolAddress(&pQ, g_Q);
    cudaGetSymbolAddress(&pK, g_K);
    cudaGetSymbolAddress(&pV, g_V);

    cudaFuncSetAttribute(gemm3_kernel, cudaFuncAttributeMaxDynamicSharedMemorySize, GEMM_SMEM);

    const int SPT = 256;
    int n4;
    n4 = BATCH * TDIM / 4;
    split_kernel<<<(n4 + SPT - 1) / SPT, SPT>>>(text, (__nv_bfloat16*)t_hi, (__nv_bfloat16*)t_lo, n4);
    n4 = BATCH * IDIM / 4;
    split_kernel<<<(n4 + SPT - 1) / SPT, SPT>>>(image, (__nv_bfloat16*)i_hi, (__nv_bfloat16*)i_lo, n4);
    n4 = TDIM * TDIM / 4;
    split_kernel<<<(n4 + SPT - 1) / SPT, SPT>>>(Wq, (__nv_bfloat16*)wq_hi, (__nv_bfloat16*)wq_lo, n4);
    n4 = TDIM * IDIM / 4;
    split_kernel<<<(n4 + SPT - 1) / SPT, SPT>>>(Wk, (__nv_bfloat16*)wk_hi, (__nv_bfloat16*)wk_lo, n4);
    split_kernel<<<(n4 + SPT - 1) / SPT, SPT>>>(Wv, (__nv_bfloat16*)wv_hi, (__nv_bfloat16*)wv_lo, n4);

    dim3 grid(TDIM / 128, BATCH / 256);
    gemm3_kernel<<<grid, 256, GEMM_SMEM>>>(
        (const __nv_bfloat16*)t_hi, (const __nv_bfloat16*)t_lo,
        (const __nv_bfloat16*)wq_hi, (const __nv_bfloat16*)wq_lo, bq, (float*)pQ, TDIM, TDIM);
    gemm3_kernel<<<grid, 256, GEMM_SMEM>>>(
        (const __nv_bfloat16*)i_hi, (const __nv_bfloat16*)i_lo,
        (const __nv_bfloat16*)wk_hi, (const __nv_bfloat16*)wk_lo, bk, (float*)pK, IDIM, TDIM);
    gemm3_kernel<<<grid, 256, GEMM_SMEM>>>(
        (const __nv_bfloat16*)i_hi, (const __nv_bfloat16*)i_lo,
        (const __nv_bfloat16*)wv_hi, (const __nv_bfloat16*)wv_lo, bv, (float*)pV, IDIM, TDIM);

    attn_ln_kernel<<<BATCH, 256>>>((const float*)pQ, (const float*)pK, (const float*)pV,
                                   text, gamma, beta, out);
}

// round 4
// speedup vs baseline: 1.7099x; 1.7099x over previous
#include <cuda_runtime.h>
#include <cuda_bf16.h>
#include <cstdint>

#define BATCH 16384
#define TDIM 1024
#define IDIM 2048

#if defined(__CUDA_ARCH_FEAT_SM103_ALL) || defined(__CUDA_ARCH_FEAT_SM100_ALL) || defined(__CUDA_ARCH_SPECIFIC__)
#define HAS_TCGEN05 1
#else
#define HAS_TCGEN05 0
#endif

// ======================= device scratch (static, no allocs) =======================
// Packed pre-swizzled operand tiles. Unit = 32KB = [hi 16KB | lo 16KB] for one
// (128-row x 64-col) bf16 tile, SW128-swizzled, indexed [kc][rowblock128].
__device__ __align__(128) __nv_bfloat16 g_text_p[16 * 128 * 16384];   // 64 MB
__device__ __align__(128) __nv_bfloat16 g_img_p[32 * 128 * 16384];    // 128 MB
__device__ __align__(128) __nv_bfloat16 g_wq_p[16 * 8 * 16384];       // 4 MB
__device__ __align__(128) __nv_bfloat16 g_wk_p[32 * 8 * 16384];       // 8 MB
__device__ __align__(128) __nv_bfloat16 g_wv_p[32 * 8 * 16384];       // 8 MB
__device__ float g_Q[BATCH * TDIM];
__device__ float g_K[BATCH * TDIM];
__device__ float g_V[BATCH * TDIM];

// ======================= PTX helpers =======================
__device__ __forceinline__ uint32_t smem_u32(const void* p) {
    uint32_t a;
    asm("{ .reg .u64 t; cvta.to.shared.u64 t, %1; cvt.u32.u64 %0, t; }" : "=r"(a) : "l"(p));
    return a;
}

__device__ __forceinline__ uint32_t elect_one_pred() {
    uint32_t pred;
    asm volatile(
        "{\n\t.reg .pred p;\n\telect.sync _|p, 0xFFFFFFFF;\n\tselp.b32 %0, 1, 0, p;\n\t}"
        : "=r"(pred));
    return pred;
}

#define TCGEN05_ALLOC(smem_result_addr, nCols) \
    asm volatile("tcgen05.alloc.cta_group::1.sync.aligned.shared::cta.b32 [%0], %1;" \
                 :: "r"((uint32_t)(smem_result_addr)), "r"((uint32_t)(nCols)) : "memory")
#define TCGEN05_DEALLOC(tmem_addr, nCols) \
    asm volatile("tcgen05.dealloc.cta_group::1.sync.aligned.b32 %0, %1;" \
                 :: "r"(tmem_addr), "r"((uint32_t)(nCols)))
#define TCGEN05_RELINQUISH() \
    asm volatile("tcgen05.relinquish_alloc_permit.cta_group::1.sync.aligned;")
#define TCGEN05_COMMIT(mbar) \
    asm volatile("tcgen05.commit.cta_group::1.mbarrier::arrive::one.shared::cluster.b64 [%0];" \
                 :: "r"((uint32_t)(mbar)) : "memory")
#define TCGEN05_FENCE_BEFORE() asm volatile("tcgen05.fence::before_thread_sync;" ::: "memory")
#define TCGEN05_FENCE_AFTER()  asm volatile("tcgen05.fence::after_thread_sync;" ::: "memory")
#define TCGEN05_WAIT_LD()      asm volatile("tcgen05.wait::ld.sync.aligned;" ::: "memory")

#define MBARRIER_INIT(mbar, count) \
    asm volatile("mbarrier.init.shared.b64 [%0], %1;" \
                 :: "r"((uint32_t)(mbar)), "r"((uint32_t)(count)) : "memory")
#define MBARRIER_INVAL(mbar) \
    asm volatile("mbarrier.inval.shared.b64 [%0];" :: "r"((uint32_t)(mbar)) : "memory")
#define MBARRIER_EXPECT_TX(mbar, tx_bytes) \
    asm volatile("mbarrier.arrive.expect_tx.shared.b64 _, [%0], %1;" \
                 :: "r"((uint32_t)(mbar)), "r"((uint32_t)(tx_bytes)) : "memory")

#define MBARRIER_WAIT_PARITY(mbar_smem_addr, phase_parity) do { \
    uint32_t _mbar = (uint32_t)(mbar_smem_addr); \
    uint32_t _parity = (uint32_t)(phase_parity); \
    uint32_t _done; \
    asm volatile( \
        "{\n\t.reg .pred p;\n\t" \
        "mbarrier.try_wait.parity.acquire.cta.shared::cta.b64 p, [%1], %2;\n\t" \
        "selp.b32 %0, 1, 0, p;\n\t}" \
        : "=r"(_done) : "r"(_mbar), "r"(_parity) : "memory"); \
    if (!_done) { \
        asm volatile( \
            "{\n\t.reg .pred P1;\n\t" \
            "WAIT_LOOP_%=:\n\t" \
            "mbarrier.try_wait.parity.acquire.cta.shared::cta.b64 P1, [%0], %1, 0x989680;\n\t" \
            "@P1 bra.uni WAIT_DONE_%=;\n\t" \
            "bra.uni WAIT_LOOP_%=;\n\t" \
            "WAIT_DONE_%=:\n\t}" \
            :: "r"(_mbar), "r"(_parity) : "memory"); \
    } \
} while (0)

#define CP_ASYNC_BULK(dst_smem, src_gmem, nbytes, mbar) \
    asm volatile("cp.async.bulk.shared::cluster.global.mbarrier::complete_tx::bytes " \
                 "[%0], [%1], %2, [%3];" \
                 :: "r"((uint32_t)(dst_smem)), "l"(src_gmem), "r"((uint32_t)(nbytes)), \
                    "r"((uint32_t)(mbar)) : "memory")

#define TCGEN05_LD_32X32B_X32(r, tmem_addr) \
    asm volatile( \
        "tcgen05.ld.sync.aligned.32x32b.x32.b32 " \
        "{%0, %1, %2, %3, %4, %5, %6, %7, " \
        " %8, %9, %10, %11, %12, %13, %14, %15, " \
        " %16, %17, %18, %19, %20, %21, %22, %23, " \
        " %24, %25, %26, %27, %28, %29, %30, %31}, [%32];" \
        : "=r"((r)[0]),  "=r"((r)[1]),  "=r"((r)[2]),  "=r"((r)[3]), \
          "=r"((r)[4]),  "=r"((r)[5]),  "=r"((r)[6]),  "=r"((r)[7]), \
          "=r"((r)[8]),  "=r"((r)[9]),  "=r"((r)[10]), "=r"((r)[11]), \
          "=r"((r)[12]), "=r"((r)[13]), "=r"((r)[14]), "=r"((r)[15]), \
          "=r"((r)[16]), "=r"((r)[17]), "=r"((r)[18]), "=r"((r)[19]), \
          "=r"((r)[20]), "=r"((r)[21]), "=r"((r)[22]), "=r"((r)[23]), \
          "=r"((r)[24]), "=r"((r)[25]), "=r"((r)[26]), "=r"((r)[27]), \
          "=r"((r)[28]), "=r"((r)[29]), "=r"((r)[30]), "=r"((r)[31]) \
        : "r"(tmem_addr))

#define SMEM_SWIZZLE_128B(byte_offset) ((byte_offset) ^ (((byte_offset) >> 3) & 0x70))

static constexpr uint64_t SMEM_DESC_BASE_SW128 =
    (uint64_t(2) << 61) | (uint64_t(1) << 46) | (uint64_t(64) << 32) | (uint64_t(1) << 16);
#define MAKE_SMEM_DESC(base_addr) \
    (SMEM_DESC_BASE_SW128 | ((uint64_t)((base_addr) >> 4) & 0x3FFF))

#if HAS_TCGEN05
__device__ __forceinline__ void mma_f16_ss(uint32_t d_tmem, uint64_t a_desc, uint64_t b_desc,
                                           uint32_t idesc, uint32_t en) {
    asm volatile(
        "{\n\t.reg .pred p;\n\tsetp.ne.u32 p, %5, 0;\n\t"
        "tcgen05.mma.cta_group::1.kind::f16 [%0], %1, %2, %3, {%4, %4, %4, %4}, p;\n\t}"
        :: "r"(d_tmem), "l"(a_desc), "l"(b_desc), "r"(idesc), "r"(0u), "r"(en)
        : "memory");
}
#endif

// ======================= pack fp32 -> swizzled bf16 hi/lo tiles =======================
__global__ void pack_kernel(const float* __restrict__ src, __nv_bfloat16* __restrict__ dst,
                            int kq8_shift, int nm128) {
    int idx = blockIdx.x * blockDim.x + threadIdx.x;
    int row = idx >> kq8_shift;
    int kq8 = idx & ((1 << kq8_shift) - 1);
    int kc = kq8 >> 3, c8 = kq8 & 7;
    int m = row >> 7, r = row & 127;
    const float4* s = (const float4*)(src + ((size_t)row << (kq8_shift + 3)) + kc * 64 + c8 * 8);
    float4 x0 = s[0], x1 = s[1];
    float f[8] = {x0.x, x0.y, x0.z, x0.w, x1.x, x1.y, x1.z, x1.w};
    __nv_bfloat16 h[8], l[8];
    #pragma unroll
    for (int i = 0; i < 8; ++i) {
        h[i] = __float2bfloat16_rn(f[i]);
        l[i] = __float2bfloat16_rn(f[i] - __bfloat162float(h[i]));
    }
    uint4 hv, lv;
    __nv_bfloat162* hp = (__nv_bfloat162*)&hv;
    __nv_bfloat162* lp = (__nv_bfloat162*)&lv;
    #pragma unroll
    for (int j = 0; j < 4; ++j) {
        hp[j] = __halves2bfloat162(h[2 * j], h[2 * j + 1]);
        lp[j] = __halves2bfloat162(l[2 * j], l[2 * j + 1]);
    }
    size_t ub = ((size_t)(kc * nm128 + m)) * 32768;  // bytes
    uint32_t off = SMEM_SWIZZLE_128B((uint32_t)(r * 128 + c8 * 16));
    *(uint4*)((char*)dst + ub + off) = hv;
    *(uint4*)((char*)dst + ub + 16384 + off) = lv;
}

// fallback-path unpack (generic pass only)
__device__ __forceinline__ float unpack_elem(const __nv_bfloat16* p, int row, int k, int nm128) {
    int kc = k >> 6, c = k & 63, m = row >> 7, r = row & 127;
    size_t ub = ((size_t)(kc * nm128 + m)) * 32768;
    uint32_t off = SMEM_SWIZZLE_128B((uint32_t)(r * 128 + c * 2));
    const char* q = (const char*)p + ub + off;
    return __bfloat162float(*(const __nv_bfloat16*)q) +
           __bfloat162float(*(const __nv_bfloat16*)(q + 16384));
}

// ======================= pipelined tcgen05 GEMM =======================
// C[16384, 1024] = A @ B^T + bias. CTA tile 256(M) x 128(N), K-chunk 64.
// 2-stage cp.async.bulk pipeline, warp0 = producer, warp1 = MMA consumer.
// Stage layout (96KB): [Ahi0 16K][Alo0 16K][Ahi1 16K][Alo1 16K][Bhi 16K][Blo 16K]
// A dedicated one-shot `done` mbarrier releases the epilogue (parity waits
// cannot count multi-phase progress — that was the Round-3 race).
#define OFF_FULL(s)  (16 + (s) * 8)
#define OFF_EMPTY(s) (32 + (s) * 8)
#define OFF_DONE     48
#define STAGE_BYTES 98304
#define GEMM_SMEM (1024 + 2 * STAGE_BYTES)
#define GEMM_IDESC 0x8200490u  // F32 accum, bf16 x bf16, M=128, N=128

__global__ __launch_bounds__(256) void gemm3_kernel(
    const __nv_bfloat16* __restrict__ Ap, const __nv_bfloat16* __restrict__ Bp,
    const float* __restrict__ bias, float* __restrict__ C, int nk) {
#if HAS_TCGEN05
    extern __shared__ char smem[];
    uint32_t sb = smem_u32(smem);
    const int tid = threadIdx.x;
    const int wid = tid >> 5;
    const int lane = tid & 31;
    const int bx = blockIdx.x;  // n-block (128 cols)
    const int by = blockIdx.y;  // m-block (256 rows)

    if (wid == 0) TCGEN05_ALLOC(sb, 256);
    __syncthreads();
    uint32_t tmem_base;
    asm volatile("ld.shared.b32 %0, [%1];" : "=r"(tmem_base) : "r"(sb));
    if (wid == 0) TCGEN05_RELINQUISH();
    if (tid == 0) {
        MBARRIER_INIT(sb + OFF_FULL(0), 1);
        MBARRIER_INIT(sb + OFF_FULL(1), 1);
        MBARRIER_INIT(sb + OFF_EMPTY(0), 1);
        MBARRIER_INIT(sb + OFF_EMPTY(1), 1);
        MBARRIER_INIT(sb + OFF_DONE, 1);
    }
    __syncthreads();

    if (wid == 0 && elect_one_pred()) {
        // -------- producer --------
        const char* srcA = (const char*)Ap;
        const char* srcB = (const char*)Bp;
        for (int kc = 0; kc < nk; ++kc) {
            int s = kc & 1, u = kc >> 1;
            MBARRIER_WAIT_PARITY(sb + OFF_EMPTY(s), (u & 1) ^ 1);
            MBARRIER_EXPECT_TX(sb + OFF_FULL(s), STAGE_BYTES);
            uint32_t st = sb + 1024 + s * STAGE_BYTES;
            const char* a = srcA + ((size_t)(kc * 128 + 2 * by)) * 32768;
            const char* b = srcB + ((size_t)(kc * 8 + bx)) * 32768;
            CP_ASYNC_BULK(st, a, 65536, sb + OFF_FULL(s));
            CP_ASYNC_BULK(st + 65536, b, 32768, sb + OFF_FULL(s));
        }
    } else if (wid == 1 && elect_one_pred()) {
        // -------- MMA consumer --------
        for (int kc = 0; kc < nk; ++kc) {
            int s = kc & 1, u = kc >> 1;
            MBARRIER_WAIT_PARITY(sb + OFF_FULL(s), u & 1);
            uint32_t st = sb + 1024 + s * STAGE_BYTES;
            uint64_t dBhi = MAKE_SMEM_DESC(st + 65536);
            uint64_t dBlo = MAKE_SMEM_DESC(st + 81920);
            #pragma unroll
            for (int sub = 0; sub < 2; ++sub) {
                uint32_t d = tmem_base + sub * 128;
                uint64_t dAhi = MAKE_SMEM_DESC(st + sub * 32768);
                uint64_t dAlo = MAKE_SMEM_DESC(st + sub * 32768 + 16384);
                #pragma unroll
                for (int ks = 0; ks < 4; ++ks)
                    mma_f16_ss(d, dAhi + ks * 2, dBhi + ks * 2, GEMM_IDESC,
                               (kc == 0 && ks == 0) ? 0u : 1u);
                #pragma unroll
                for (int ks = 0; ks < 4; ++ks)
                    mma_f16_ss(d, dAhi + ks * 2, dBlo + ks * 2, GEMM_IDESC, 1u);
                #pragma unroll
                for (int ks = 0; ks < 4; ++ks)
                    mma_f16_ss(d, dAlo + ks * 2, dBhi + ks * 2, GEMM_IDESC, 1u);
            }
            if (kc == nk - 1) TCGEN05_COMMIT(sb + OFF_DONE);  // tracks ALL prior MMAs
            TCGEN05_COMMIT(sb + OFF_EMPTY(s));
        }
    }

    // -------- epilogue: single-phase done barrier (no parity aliasing) --------
    MBARRIER_WAIT_PARITY(sb + OFF_DONE, 0);
    TCGEN05_FENCE_AFTER();
    {
        int sub = wid >> 2, w4 = wid & 3;
        int row = by * 256 + sub * 128 + w4 * 32 + lane;
        int n0 = bx * 128;
        float* Crow = C + (size_t)row * TDIM + n0;
        uint32_t cb = tmem_base + sub * 128;
        #pragma unroll
        for (int g2 = 0; g2 < 4; ++g2) {
            uint32_t r[32];
            TCGEN05_LD_32X32B_X32(r, cb + g2 * 32);
            TCGEN05_WAIT_LD();
            #pragma unroll
            for (int c = 0; c < 32; ++c)
                Crow[g2 * 32 + c] = __uint_as_float(r[c]) + __ldg(&bias[n0 + g2 * 32 + c]);
        }
    }
    TCGEN05_FENCE_BEFORE();
    __syncthreads();
    if (tid == 0) {
        MBARRIER_INVAL(sb + OFF_FULL(0));
        MBARRIER_INVAL(sb + OFF_FULL(1));
        MBARRIER_INVAL(sb + OFF_EMPTY(0));
        MBARRIER_INVAL(sb + OFF_EMPTY(1));
        MBARRIER_INVAL(sb + OFF_DONE);
    }
    __syncthreads();
    if (wid == 0) TCGEN05_DEALLOC(tmem_base, 256);
#else
    // ---------- SIMT fallback (generic pass; correct, never expected to run) ----------
    extern __shared__ char smem[];
    float* sA = (float*)smem;                  // [128][33]
    float* sB = (float*)(smem + 128 * 33 * 4); // [128][33]
    const int tid = threadIdx.x;
    const int tx = tid & 15, ty = tid >> 4;
    const int m0 = blockIdx.y * 256;
    const int n0 = blockIdx.x * 128;
    const int Kg = nk * 64;

    for (int h = 0; h < 2; ++h) {
        float acc[8][8];
        #pragma unroll
        for (int i = 0; i < 8; ++i)
            #pragma unroll
            for (int j = 0; j < 8; ++j) acc[i][j] = 0.f;

        for (int k0 = 0; k0 < Kg; k0 += 32) {
            __syncthreads();
            for (int i = tid; i < 128 * 32; i += 256) {
                int r = i >> 5, c = i & 31;
                sA[r * 33 + c] = unpack_elem(Ap, m0 + h * 128 + r, k0 + c, 128);
                sB[r * 33 + c] = unpack_elem(Bp, n0 + r, k0 + c, 8);
            }
            __syncthreads();
            #pragma unroll 8
            for (int kk = 0; kk < 32; ++kk) {
                float a[8], bb[8];
                #pragma unroll
                for (int i = 0; i < 8; ++i) a[i] = sA[(ty * 8 + i) * 33 + kk];
                #pragma unroll
                for (int j = 0; j < 8; ++j) bb[j] = sB[(tx * 8 + j) * 33 + kk];
                #pragma unroll
                for (int i = 0; i < 8; ++i)
                    #pragma unroll
                    for (int j = 0; j < 8; ++j) acc[i][j] = fmaf(a[i], bb[j], acc[i][j]);
            }
        }
        #pragma unroll
        for (int i = 0; i < 8; ++i) {
            int row = m0 + h * 128 + ty * 8 + i;
            float* Crow = C + (size_t)row * TDIM + n0 + tx * 8;
            #pragma unroll
            for (int j = 0; j < 8; ++j)
                Crow[j] = acc[i][j] + bias[n0 + tx * 8 + j];
        }
    }
#endif
}

// ======================= fused attention + residual + LayerNorm =======================
__global__ __launch_bounds__(256) void attn_ln_kernel(
    const float* __restrict__ Q, const float* __restrict__ K, const float* __restrict__ V,
    const float* __restrict__ text, const float* __restrict__ gamma,
    const float* __restrict__ beta, float* __restrict__ out) {
    __shared__ float sQ[1024], sK[1024], sV[1024];
    __shared__ float sAttn[8][8];
    __shared__ float red[16];
    const int b = blockIdx.x;
    const int tid = threadIdx.x;
    const int w = tid >> 5, lane = tid & 31;
    const size_t base = (size_t)b * 1024;

    for (int i = tid; i < 1024; i += 256) {
        sQ[i] = Q[base + i];
        sK[i] = K[base + i];
        sV[i] = V[base + i];
    }
    __syncthreads();

    float sc[8];
    #pragma unroll
    for (int g = 0; g < 8; ++g) {
        float s = 0.f;
        #pragma unroll
        for (int d = 0; d < 4; ++d) {
            int dd = lane + d * 32;
            s += sQ[w * 128 + dd] * sK[g * 128 + dd];
        }
        #pragma unroll
        for (int o = 16; o; o >>= 1) s += __shfl_xor_sync(0xffffffffu, s, o);
        sc[g] = s * 0.08838834764831845f;
    }
    float m = sc[0];
    #pragma unroll
    for (int g = 1; g < 8; ++g) m = fmaxf(m, sc[g]);
    float den = 0.f;
    #pragma unroll
    for (int g = 0; g < 8; ++g) { sc[g] = __expf(sc[g] - m); den += sc[g]; }
    float inv = 1.f / den;
    if (lane < 8) sAttn[w][lane] = sc[lane] * inv;
    __syncthreads();

    float xv[4];
    float sum = 0.f, sumsq = 0.f;
    #pragma unroll
    for (int j = 0; j < 4; ++j) {
        int d = tid + j * 256;
        int h = d >> 7, dd = d & 127;
        float a = 0.f;
        #pragma unroll
        for (int g = 0; g < 8; ++g) a += sAttn[h][g] * sV[g * 128 + dd];
        float x = text[base + d] + a;
        xv[j] = x;
        sum += x;
        sumsq += x * x;
    }
    #pragma unroll
    for (int o = 16; o; o >>= 1) {
        sum += __shfl_xor_sync(0xffffffffu, sum, o);
        sumsq += __shfl_xor_sync(0xffffffffu, sumsq, o);
    }
    if (lane == 0) { red[w] = sum; red[8 + w] = sumsq; }
    __syncthreads();
    float ts = 0.f, tq = 0.f;
    #pragma unroll
    for (int i = 0; i < 8; ++i) { ts += red[i]; tq += red[8 + i]; }
    float mu = ts * (1.f / 1024.f);
    float var = tq * (1.f / 1024.f) - mu * mu;
    float rstd = rsqrtf(var + 1e-5f);
    #pragma unroll
    for (int j = 0; j < 4; ++j) {
        int d = tid + j * 256;
        out[base + d] = (xv[j] - mu) * rstd * gamma[d] + beta[d];
    }
}

// ======================= host =======================
extern "C" void kernel_launch(void* const* d_in, const int* in_sizes, int n_in,
                              void* d_out, int out_size) {
    const float* text  = (const float*)d_in[0];
    const float* image = (const float*)d_in[1];
    const float* Wq    = (const float*)d_in[2];
    const float* bq    = (const float*)d_in[3];
    const float* Wk    = (const float*)d_in[4];
    const float* bk    = (const float*)d_in[5];
    const float* Wv    = (const float*)d_in[6];
    const float* bv    = (const float*)d_in[7];
    const float* gamma = (const float*)d_in[8];
    const float* beta  = (const float*)d_in[9];
    float* out = (float*)d_out;

    void *tp, *ip, *wqp, *wkp, *wvp, *pQ, *pK, *pV;
    cudaGetSymbolAddress(&tp, g_text_p);
    cudaGetSymbolAddress(&ip, g_img_p);
    cudaGetSymbolAddress(&wqp, g_wq_p);
    cudaGetSymbolAddress(&wkp, g_wk_p);
    cudaGetSymbolAddress(&wvp, g_wv_p);
    cudaGetSymbolAddress(&pQ, g_Q);
    cudaGetSymbolAddress(&pK, g_K);
    cudaGetSymbolAddress(&pV, g_V);

    cudaFuncSetAttribute(gemm3_kernel, cudaFuncAttributeMaxDynamicSharedMemorySize, GEMM_SMEM);

    // pack: (rows*K/8) threads each
    pack_kernel<<<BATCH * TDIM / 8 / 256, 256>>>(text, (__nv_bfloat16*)tp, 7, 128);
    pack_kernel<<<BATCH * IDIM / 8 / 256, 256>>>(image, (__nv_bfloat16*)ip, 8, 128);
    pack_kernel<<<TDIM * TDIM / 8 / 256, 256>>>(Wq, (__nv_bfloat16*)wqp, 7, 8);
    pack_kernel<<<TDIM * IDIM / 8 / 256, 256>>>(Wk, (__nv_bfloat16*)wkp, 8, 8);
    pack_kernel<<<TDIM * IDIM / 8 / 256, 256>>>(Wv, (__nv_bfloat16*)wvp, 8, 8);

    dim3 grid(TDIM / 128, BATCH / 256);
    gemm3_kernel<<<grid, 256, GEMM_SMEM>>>((const __nv_bfloat16*)tp, (const __nv_bfloat16*)wqp,
                                           bq, (float*)pQ, 16);
    gemm3_kernel<<<grid, 256, GEMM_SMEM>>>((const __nv_bfloat16*)ip, (const __nv_bfloat16*)wkp,
                                           bk, (float*)pK, 32);
    gemm3_kernel<<<grid, 256, GEMM_SMEM>>>((const __nv_bfloat16*)ip, (const __nv_bfloat16*)wvp,
                                           bv, (float*)pV, 32);

    attn_ln_kernel<<<BATCH, 256>>>((const float*)pQ, (const float*)pK, (const float*)pV,
                                   text, gamma, beta, out);
}